// round 17
// baseline (speedup 1.0000x reference)
#include <cuda_runtime.h>
#include <cuda_bf16.h>
#include <cstdint>

// Problem constants
#define BB    32
#define DD    384
#define TTOT  4096
#define TTILE 64
#define NTHR  256
#define KK    256
#define KC    128
#define NCHK  3
#define TAU   6.0f
#define MAXF  131072
#define NPART 2048

// int8 quantization scales
#define QA    (127.0f / 6.0f)     // z multiplier
#define QC    (127.0f / 5.0f)     // codebook multiplier
#define S2    (2.0f * (6.0f / 127.0f) * (5.0f / 127.0f))

#define Q_ELEMS   ((size_t)BB * DD * TTOT)
#define IDX_ELEMS ((size_t)BB * TTOT)

// SMEM layout (bytes)
#define A_OFF     0        // z s8, rows=t(64) x 128B, swizzled (8K)
#define B0_OFF    8192     // cb s8 buf0 (32K)
#define B1_OFF    40960    // cb s8 buf1 (32K)
#define ES_OFF    73728    // e2 [256] f32
#define REDV_OFF  74752    // [64][4] f32
#define REDK_OFF  75776    // [64][4] i32
#define BV_OFF    76800    // [64] f32
#define BK_OFF    77056    // [64] i32
#define CC_OFF    77312    // [64] i32
#define CL_OFF    77568    // [64][7] i32
#define LRED_OFF  79360    // [256] f32
#define SMEM_SZ   80384    // occ 2 @ 256 thr

// Scratch
__device__ float  g_ct[DD * KK];
__device__ float  g_e2f[KK];
__device__ int    g_idx[BB * TTOT];
__device__ float  g_partials[NPART];
__device__ int    g_nflag;
__device__ int    g_fpt[MAXF];
__device__ int    g_fcnt[MAXF];
__device__ float  g_fsv[MAXF];          // screening-best score (sans x2) at flag time
__device__ int    g_fcand[MAXF][8];
__device__ float  g_ldelta[MAXF];
__device__ signed char g_bq[NCHK * KK * KC];  // pre-swizzled s8 codebook

static __device__ __forceinline__ uint32_t smem_u32(const void* p) {
    uint32_t a;
    asm("{ .reg .u64 t; cvta.to.shared.u64 t, %1; cvt.u32.u64 %0, t; }"
        : "=r"(a) : "l"(p));
    return a;
}
static __device__ __forceinline__ int q8(float v, float s) {
    int i = __float2int_rn(v * s);
    return i < -127 ? -127 : (i > 127 ? 127 : i);
}

#define CPASYNC16(dst, src) \
    asm volatile("cp.async.cg.shared.global [%0], [%1], 16;" \
        :: "r"(dst), "l"(src) : "memory")
#define CPCOMMIT  asm volatile("cp.async.commit_group;" ::: "memory")
#define CPWAIT0   asm volatile("cp.async.wait_group 0;" ::: "memory")
#define CPWAIT1   asm volatile("cp.async.wait_group 1;" ::: "memory")

#define LDSM4(r, ad) \
    asm volatile("ldmatrix.sync.aligned.m8n8.x4.shared.b16 {%0,%1,%2,%3}, [%4];" \
        : "=r"((r)[0]), "=r"((r)[1]), "=r"((r)[2]), "=r"((r)[3]) : "r"(ad))

#define MMAS8(d, a, b0, b1) \
    asm volatile("mma.sync.aligned.m16n8k32.row.col.s32.s8.s8.s32 " \
        "{%0,%1,%2,%3},{%4,%5,%6,%7},{%8,%9},{%0,%1,%2,%3};" \
        : "+r"((d)[0]), "+r"((d)[1]), "+r"((d)[2]), "+r"((d)[3]) \
        : "r"((a)[0]), "r"((a)[1]), "r"((a)[2]), "r"((a)[3]), "r"(b0), "r"(b1))

// ---- prep: g_ct transpose + XLA-emulated e2 + s8 swizzled codebook + reset ----
__global__ void vq_prep(const float* __restrict__ cb) {
    const unsigned FULL = 0xffffffffu;
    int bid = blockIdx.x;
    if (bid < 384) {
        int gid = bid * 256 + threadIdx.x;
        int k = gid / DD;
        int d = gid - k * DD;
        g_ct[d * KK + k] = cb[gid];
    } else if (bid < 416) {
        int lane = threadIdx.x & 31;
        int warp = threadIdx.x >> 5;
        int row = (bid - 384) * 8 + warp;
        const float* c = cb + (size_t)row * DD;
        float s = 0.f;
#pragma unroll
        for (int j = 0; j < DD / 32; ++j) {
            float v = c[lane + 32 * j];
            s = fmaf(v, v, s);
        }
#pragma unroll
        for (int off = 16; off; off >>= 1) s += __shfl_down_sync(FULL, s, off);
        if (lane == 0) g_e2f[row] = s;
    } else if (bid < 800) {
        int gid = (bid - 416) * 256 + threadIdx.x;   // < 98304
        int k = gid / DD;
        int d = gid - k * DD;
        int q = q8(cb[gid], QC);
        int c   = d >> 7;        // chunk of 128 d
        int din = d & 127;       // byte within row
        g_bq[c * (KK * KC) + k * KC + (din ^ ((k & 7) * 16))] = (signed char)q;
    } else {
        if (threadIdx.x == 0) g_nflag = 0;
    }
}

// ---- main: int8 mma.sync screening, occ-2, B double-buffered ----
__global__ __launch_bounds__(NTHR, 2) void vq_main(const float* __restrict__ z) {
    extern __shared__ char smem[];
    const uint32_t sb = smem_u32(smem);
    const int tid  = threadIdx.x;
    const int lane = tid & 31;
    const int w    = tid >> 5;
    const int wm   = w & 1;    // t slice (32 t)
    const int wn   = w >> 1;   // code slice (64 codes)
    const int b    = blockIdx.y;
    const int tg   = blockIdx.x * TTILE;

    ((float*)(smem + ES_OFF))[tid] = g_e2f[tid];

    const float* zb = z + (size_t)b * DD * TTOT + tg;
    const int zk = tid >> 4;        // 0..15 -> d = 8*zk + p
    const int zt0 = (tid & 15) * 4; // t0 (4 consecutive t)

    const uint32_t bbase[2] = { sb + B0_OFF, sb + B1_OFF };

    int acc[2][8][4];   // [mi][n8 tile][frag], s32
#pragma unroll
    for (int i = 0; i < 2; ++i)
#pragma unroll
        for (int j = 0; j < 8; ++j)
#pragma unroll
            for (int q = 0; q < 4; ++q) acc[i][j][q] = 0;

    float x2acc = 0.f;

#define ISSUE_B(c, bbuf)                                                           \
    {                                                                              \
        const char* sh = (const char*)(g_bq + (c) * (KK * KC));                    \
        uint32_t dh = (bbuf) + (unsigned)tid * 16;                                 \
        _Pragma("unroll")                                                          \
        for (int j = 0; j < 8; ++j)                                                \
            CPASYNC16(dh + 4096u * j, sh + (tid + NTHR * j) * 16);                 \
        CPCOMMIT;                                                                  \
    }

    ISSUE_B(0, bbase[0]);

    for (int c = 0; c < NCHK; ++c) {
        __syncthreads();    // MMA(c-1) done with A and B[(c+1)&1]

        if (c + 1 < NCHK) ISSUE_B(c + 1, bbase[(c + 1) & 1]);

        // load + quantize z(c) -> A tile (s8, rows=t, 128B swizzled) + x2
        {
            float zr[32];
#pragma unroll
            for (int p = 0; p < 8; ++p)
                *(float4*)&zr[p * 4] =
                    *(const float4*)(zb + (size_t)(c * KC + 8 * zk + p) * TTOT + zt0);
#pragma unroll
            for (int jt = 0; jt < 4; ++jt) {
                const int t = zt0 + jt;
                unsigned w0 = 0, w1 = 0;
#pragma unroll
                for (int p = 0; p < 4; ++p) {
                    float f = zr[p * 4 + jt];
                    x2acc = fmaf(f, f, x2acc);
                    w0 |= ((unsigned)(q8(f, QA) & 255)) << (p * 8);
                }
#pragma unroll
                for (int p = 4; p < 8; ++p) {
                    float f = zr[p * 4 + jt];
                    x2acc = fmaf(f, f, x2acc);
                    w1 |= ((unsigned)(q8(f, QA) & 255)) << ((p - 4) * 8);
                }
                const unsigned sw = (unsigned)(t & 7) * 16;
                *(unsigned*)(smem + A_OFF + t * 128 + (((unsigned)(8 * zk)) ^ sw)) = w0;
                *(unsigned*)(smem + A_OFF + t * 128 + (((unsigned)(8 * zk + 4)) ^ sw)) = w1;
            }
        }

        if (c + 1 < NCHK) { CPWAIT1; } else { CPWAIT0; }
        __syncthreads();    // A + B(c) visible

        // MMA: 4 k32 steps over this 128-d chunk
        const uint32_t bcur = bbase[c & 1];
#pragma unroll
        for (int ks = 0; ks < 4; ++ks) {
            uint32_t ah[2][4];
#pragma unroll
            for (int mi = 0; mi < 2; ++mi) {
                int row = wm * 32 + mi * 16 + ((lane >> 3) & 1) * 8 + (lane & 7);
                unsigned kb = (unsigned)ks * 32 + ((lane >> 4) & 1) * 16;
                uint32_t ad = sb + A_OFF + (unsigned)row * 128 + (kb ^ ((unsigned)(row & 7) * 16));
                LDSM4(ah[mi], ad);
            }
#pragma unroll
            for (int ng = 0; ng < 4; ++ng) {
                int n = wn * 64 + ng * 16 + ((lane >> 4) & 1) * 8 + (lane & 7);
                unsigned kb = (unsigned)ks * 32 + ((lane >> 3) & 1) * 16;
                uint32_t bd = bcur + (unsigned)n * 128 + (kb ^ ((unsigned)(n & 7) * 16));
                uint32_t bh[4];
                LDSM4(bh, bd);
#pragma unroll
                for (int mi = 0; mi < 2; ++mi) {
#pragma unroll
                    for (int t2 = 0; t2 < 2; ++t2)
                        MMAS8(acc[mi][ng * 2 + t2], ah[mi], bh[t2 * 2], bh[t2 * 2 + 1]);
                }
            }
        }
    }
#undef ISSUE_B

    // ---- epilogue: argmin over 256 codes (score = e2 - S2*dot) ----
    const float* es = (const float*)(smem + ES_OFF);
    float* redv = (float*)(smem + REDV_OFF);
    int*   redk = (int*)(smem + REDK_OFF);
    float* bestv_s = (float*)(smem + BV_OFF);
    int*   bestk_s = (int*)(smem + BK_OFF);
    int*   ccnt = (int*)(smem + CC_OFF);
    int*   clst = (int*)(smem + CL_OFF);
    float* lred = (float*)(smem + LRED_OFF);
    const unsigned FULL = 0xffffffffu;

    float bv[4];
    int   bk[4];
#pragma unroll
    for (int j = 0; j < 4; ++j) { bv[j] = 3.4e38f; bk[j] = KK; }
#pragma unroll
    for (int mi = 0; mi < 2; ++mi)
#pragma unroll
        for (int nt = 0; nt < 8; ++nt)
#pragma unroll
            for (int ci = 0; ci < 4; ++ci) {
                int code = wn * 64 + nt * 8 + (lane & 3) * 2 + (ci & 1);
                int j = mi * 2 + (ci >> 1);
                float sc = es[code] - S2 * (float)acc[mi][nt][ci];
                if (sc < bv[j] || (sc == bv[j] && code < bk[j])) { bv[j] = sc; bk[j] = code; }
            }
#pragma unroll
    for (int j = 0; j < 4; ++j) {
#pragma unroll
        for (int off = 1; off < 4; off <<= 1) {
            float ov = __shfl_xor_sync(FULL, bv[j], off);
            int   ok = __shfl_xor_sync(FULL, bk[j], off);
            if (ov < bv[j] || (ov == bv[j] && ok < bk[j])) { bv[j] = ov; bk[j] = ok; }
        }
    }
    if ((lane & 3) == 0) {
#pragma unroll
        for (int j = 0; j < 4; ++j) {
            int t = wm * 32 + (j >> 1) * 16 + (lane >> 2) + (j & 1) * 8;
            redv[t * 4 + wn] = bv[j];
            redk[t * 4 + wn] = bk[j];
        }
    }
    __syncthreads();
    if (tid < TTILE) {
        float fv = redv[tid * 4];
        int   fk = redk[tid * 4];
#pragma unroll
        for (int q = 1; q < 4; ++q) {
            float v = redv[tid * 4 + q];
            int   k = redk[tid * 4 + q];
            if (v < fv || (v == fv && k < fk)) { fv = v; fk = k; }
        }
        bestv_s[tid] = fv;
        bestk_s[tid] = fk;
        ccnt[tid] = 0;
        g_idx[b * TTOT + tg + tid] = fk;
    }
    __syncthreads();

    // candidate scan (score <= best + TAU, code != best)
#pragma unroll
    for (int mi = 0; mi < 2; ++mi)
#pragma unroll
        for (int nt = 0; nt < 8; ++nt)
#pragma unroll
            for (int ci = 0; ci < 4; ++ci) {
                int code = wn * 64 + nt * 8 + (lane & 3) * 2 + (ci & 1);
                int t = wm * 32 + mi * 16 + (lane >> 2) + ((ci >> 1) ? 8 : 0);
                float sc = es[code] - S2 * (float)acc[mi][nt][ci];
                if (sc <= bestv_s[t] + TAU && code != bestk_s[t]) {
                    int slot = atomicAdd(&ccnt[t], 1);
                    if (slot < 7) clst[t * 7 + slot] = code;
                }
            }
    __syncthreads();

    if (tid < TTILE && ccnt[tid] > 0) {
        int slot = atomicAdd(&g_nflag, 1);
        if (slot < MAXF) {
            g_fpt[slot] = (b << 12) | (tg + tid);
            g_fsv[slot] = bestv_s[tid];
            int cnum = ccnt[tid];
            if (cnum <= 7) {
                g_fcand[slot][0] = bestk_s[tid];
#pragma unroll
                for (int j = 0; j < 7; ++j)
                    if (j < cnum) g_fcand[slot][1 + j] = clst[tid * 7 + j];
                g_fcnt[slot] = cnum + 1;
            } else {
                g_fcnt[slot] = -1;   // scan all 256
            }
        }
    }

    // loss partial: sum x2 + sum best scores
    lred[tid] = x2acc + ((tid < TTILE) ? bestv_s[tid] : 0.f);
    __syncthreads();
    for (int s = NTHR / 2; s > 0; s >>= 1) {
        if (tid < s) lred[tid] += lred[tid + s];
        __syncthreads();
    }
    if (tid == 0) g_partials[b * gridDim.x + blockIdx.x] = lred[0];
}

// ---- refine: reference-fp32-EMULATED re-decision of flagged points ----
__global__ void vq_refine(const float* __restrict__ z, const float* __restrict__ cb) {
    const unsigned FULL = 0xffffffffu;
    __shared__ float zsh[4][DD];
    const int lane = threadIdx.x & 31;
    const int warp = threadIdx.x >> 5;
    const int warps_total = gridDim.x * (blockDim.x >> 5);
    const int wg = blockIdx.x * (blockDim.x >> 5) + warp;

    int n = g_nflag;
    if (n > MAXF) n = MAXF;

    for (int e = wg; e < n; e += warps_total) {
        const int pt = g_fpt[e];
        const int b = pt >> 12;
        const int t = pt & 4095;
        const float* zp = z + (size_t)b * DD * TTOT + t;

        for (int d = lane; d < DD; d += 32) zsh[warp][d] = zp[(size_t)d * TTOT];
        __syncwarp();

        float s = 0.f;
#pragma unroll
        for (int j = 0; j < DD / 32; ++j) {
            float v = zsh[warp][lane + 32 * j];
            s = fmaf(v, v, s);
        }
#pragma unroll
        for (int off = 16; off; off >>= 1) s += __shfl_down_sync(FULL, s, off);
        const float x2f = __shfl_sync(FULL, s, 0);

        const int cnt = g_fcnt[e];
        const int ncand = (cnt < 0) ? KK : cnt;

        float bestdf = 3.4e38f;
        int bestk = 1 << 30;
        for (int c = lane; c < ncand; c += 32) {
            const int k = (cnt < 0) ? c : g_fcand[e][c];
            const float* ck = cb + (size_t)k * DD;
            float dot = 0.f;
#pragma unroll 8
            for (int d = 0; d < DD; ++d) dot = fmaf(zsh[warp][d], ck[d], dot);
            float df = __fadd_rn(__fsub_rn(x2f, 2.0f * dot), g_e2f[k]);
            if (df < bestdf || (df == bestdf && k < bestk)) { bestdf = df; bestk = k; }
        }
#pragma unroll
        for (int off = 16; off; off >>= 1) {
            float od = __shfl_down_sync(FULL, bestdf, off);
            int   ok = __shfl_down_sync(FULL, bestk, off);
            if (od < bestdf || (od == bestdf && ok < bestk)) { bestdf = od; bestk = ok; }
        }
        if (lane == 0) {
            g_idx[b * TTOT + t] = bestk;
            g_ldelta[e] = bestdf - (x2f + g_fsv[e]);  // exact dist replaces screen-implied
        }
        __syncwarp();
    }
}

// ---- writer: gather-only quantize + indices ----
__global__ __launch_bounds__(256) void vq_write(float* __restrict__ out) {
    const int tid = threadIdx.x;
    const int b  = blockIdx.y;
    const int dz = blockIdx.z;                      // 0..7, 48 d each
    const int t4 = (blockIdx.x * 256 + tid) << 2;

    const int4 kk = *(const int4*)&g_idx[b * TTOT + t4];

    if (dz == 0) {
        float4 fi = make_float4((float)kk.x, (float)kk.y, (float)kk.z, (float)kk.w);
        *(float4*)&out[Q_ELEMS + (size_t)b * TTOT + t4] = fi;
    }

    float* ob = out + (size_t)b * DD * TTOT + t4;
    const int dlo = dz * (DD / 8);
#pragma unroll 4
    for (int d = dlo; d < dlo + DD / 8; ++d) {
        const float* row = g_ct + d * KK;
        float4 q = make_float4(row[kk.x], row[kk.y], row[kk.z], row[kk.w]);
        *(float4*)&ob[(size_t)d * TTOT] = q;
    }
}

// ---- finalize: 1024-thread deterministic reduction ----
__global__ void vq_finalize(float* __restrict__ out) {
    __shared__ float s[1024];
    int n = g_nflag;
    if (n > MAXF) n = MAXF;
    float a = 0.f;
    for (int j = threadIdx.x; j < NPART; j += 1024) a += g_partials[j];
    for (int e = threadIdx.x; e < n; e += 1024) a += g_ldelta[e];
    s[threadIdx.x] = a;
    __syncthreads();
    for (int st = 512; st > 0; st >>= 1) {
        if (threadIdx.x < st) s[threadIdx.x] += s[threadIdx.x + st];
        __syncthreads();
    }
    if (threadIdx.x == 0)
        out[Q_ELEMS + IDX_ELEMS] =
            0.25f * s[0] / (float)((size_t)BB * TTOT * DD);
}

extern "C" void kernel_launch(void* const* d_in, const int* in_sizes, int n_in,
                              void* d_out, int out_size) {
    const float* z  = (const float*)d_in[0];
    const float* cb = (const float*)d_in[1];
    float* out = (float*)d_out;

    cudaFuncSetAttribute(vq_main, cudaFuncAttributeMaxDynamicSharedMemorySize, SMEM_SZ);

    vq_prep<<<801, 256>>>(cb);
    dim3 grid(TTOT / TTILE, BB);
    vq_main<<<grid, NTHR, SMEM_SZ>>>(z);
    vq_refine<<<2048, 128>>>(z, cb);
    dim3 wgrid(TTOT / 1024, BB, 8);
    vq_write<<<wgrid, 256>>>(out);
    vq_finalize<<<1, 1024>>>(out);
}